// round 8
// baseline (speedup 1.0000x reference)
#include <cuda_runtime.h>

// Problem constants (fixed by the reference).
#define NB 4096
#define NT 512
#define NI 5
#define NH 16
#define WND 32                  // xproj window (steps) per double-buffer half
#define NWND (NT / WND)         // 16 windows
#define FULLMASK 0xffffffffu

typedef unsigned long long ull;

// ---- fast activations ----
__device__ __forceinline__ float tanh_fast(float x) {
    float y;
    asm("tanh.approx.f32 %0, %1;" : "=f"(y) : "f"(x));
    return y;
}
__device__ __forceinline__ float sig_acc(float x) {   // epilogue only
    float e = __expf(-x);
    return __fdividef(1.0f, 1.0f + e);
}

// ---- packed f32x2 helpers (Blackwell FFMA2) ----
__device__ __forceinline__ ull pack2(float lo, float hi) {
    ull r;
    asm("mov.b64 %0, {%1, %2};" : "=l"(r) : "f"(lo), "f"(hi));
    return r;
}
__device__ __forceinline__ void unpack2(ull v, float& lo, float& hi) {
    asm("mov.b64 {%0, %1}, %2;" : "=f"(lo), "=f"(hi) : "l"(v));
}
__device__ __forceinline__ void fma2(ull& acc, ull a, ull b) {
    asm("fma.rn.f32x2 %0, %1, %2, %0;" : "+l"(acc) : "l"(a), "l"(b));
}
__device__ __forceinline__ ull mul2(ull a, ull b) {
    ull r;
    asm("mul.rn.f32x2 %0, %1, %2;" : "=l"(r) : "l"(a), "l"(b));
    return r;
}
__device__ __forceinline__ ull add2(ull a, ull b) {
    ull r;
    asm("add.rn.f32x2 %0, %1, %2;" : "=l"(r) : "l"(a), "l"(b));
    return r;
}
__device__ __forceinline__ float hsum2(ull v) {
    float lo, hi;
    unpack2(v, lo, hi);
    return lo + hi;
}

// Input-projection weights for one lane (warp 1 only).
struct XW {
    float wA[NI], wB[NI];
    float bA, bB;
};

// Two-warp LSTM over the ONLY batch row that matters (b = NB-1).
// Warp 0: serial recurrence. State lane k computes i,g AND f locally
//         (f = accC; no shfl on the c-update path). Upper lane k+16
//         computes o and ships the FINISHED so = 0.5*tanh+0.5 via
//         shfl_down, hidden under the ig->c->tanh(c) segment.
// Warp 1: precomputes pre-activations into double-buffered windows.
//         Its upper-lane aA IS the f-row pre-activation -> side array.
__global__ void __launch_bounds__(64, 1) lstm_last_row_kernel(
    const float* __restrict__ x,      // (B, T, I)
    const float* __restrict__ W_ih,   // (64, 5)
    const float* __restrict__ W_hh,   // (64, 16)
    const float* __restrict__ b_ih,   // (64,)
    const float* __restrict__ b_hh,   // (64,)
    const float* __restrict__ W_lin,  // (5, 16)
    const float* __restrict__ b_lin,  // (5,)
    float* __restrict__ out)          // (5,)
{
    __shared__ __align__(16) float  xs[NT * NI];        // 10 KB raw x row
    __shared__ __align__(16) float4 xp4[2][WND * 32];   // 32 KB (aA,0,aB,0)
    __shared__ __align__(16) float  xpc[2][WND * 16];   // 4 KB f-row preacts
    __shared__ float hfin[NH];

    const int tid  = threadIdx.x;
    const int warp = tid >> 5;
    const int lane = tid & 31;
    const int k    = lane & 15;

    // Cooperative stage of x[B-1,:,:] (both warps).
    {
        const float4* src4 = reinterpret_cast<const float4*>(
            x + (size_t)(NB - 1) * NT * NI);
        float4* dst4 = reinterpret_cast<float4*>(xs);
        #pragma unroll 4
        for (int i = tid; i < (NT * NI) / 4; i += 64) dst4[i] = src4[i];
    }

    // Gate rows: g0 = lane -> i_k (lane<16) | f_k (lane>=16)  [0.5-scaled]
    //            g1 = lane+32 -> g_k (lane<16) | o_k (lane>=16)
    //            gC = k+16 -> f_k for EVERY lane               [0.5-scaled]
    const int g0 = lane;
    const int g1 = lane + 32;
    const int gC = k + 16;
    const float sB = (lane < 16) ? 1.0f : 0.5f;   // g full-scale, o pre-halved

    // Warp-1 state: input-projection weights (pre-scaled).
    XW xw;
    if (warp == 1) {
        #pragma unroll
        for (int i = 0; i < NI; ++i) {
            xw.wA[i] = 0.5f * W_ih[g0 * NI + i];
            xw.wB[i] = sB   * W_ih[g1 * NI + i];
        }
        xw.bA = 0.5f * (b_ih[g0] + b_hh[g0]);
        xw.bB = sB   * (b_ih[g1] + b_hh[g1]);
    }

    // Warp-0 state: recurrent weights, (even,odd)-packed, pre-scaled.
    ull wA2[NH / 2], wB2[NH / 2], wC2[NH / 2];
    if (warp == 0) {
        #pragma unroll
        for (int p = 0; p < NH / 2; ++p) {
            wA2[p] = pack2(0.5f * W_hh[g0 * NH + 2 * p],
                           0.5f * W_hh[g0 * NH + 2 * p + 1]);
            wB2[p] = pack2(sB * W_hh[g1 * NH + 2 * p],
                           sB * W_hh[g1 * NH + 2 * p + 1]);
            wC2[p] = pack2(0.5f * W_hh[gC * NH + 2 * p],
                           0.5f * W_hh[gC * NH + 2 * p + 1]);
        }
    }

    __syncthreads();   // xs staged

    // Warp 1 window fill: (aA,0,aB,0) per lane; upper-lane aA == f-preact.
    auto fill_window = [&](int w) {
        float4* d4 = xp4[w & 1];
        float*  dc = xpc[w & 1];
        #pragma unroll 4
        for (int tl = 0; tl < WND; ++tl) {
            const float* xt = &xs[(w * WND + tl) * NI];
            float a0 = xw.bA, a1 = xw.bB;
            #pragma unroll
            for (int i = 0; i < NI; ++i) {
                const float xv = xt[i];
                a0 = fmaf(xw.wA[i], xv, a0);
                a1 = fmaf(xw.wB[i], xv, a1);
            }
            d4[tl * 32 + lane] = make_float4(a0, 0.0f, a1, 0.0f);
            if (lane >= 16) dc[tl * 16 + (lane - 16)] = a0;
        }
    };

    if (warp == 1) fill_window(0);
    __syncthreads();

    float h = 0.0f, c = 0.0f;

    for (int w = 0; w < NWND; ++w) {
        if (warp == 0) {
            const float4* b4 = xp4[w & 1];
            const float*  bc = xpc[w & 1];
            #pragma unroll 4
            for (int tl = 0; tl < WND; ++tl) {
                // Pre-activations: LDS.128 + LDS.32, ready acc inits.
                const float4 q  = b4[tl * 32 + lane];
                const float  qc = bc[tl * 16 + k];
                ull accA0 = pack2(q.x, q.y);    // (a_i|a_f, 0)
                ull accB0 = pack2(q.z, q.w);    // (a_g|a_o, 0)
                ull accC0 = pack2(qc, 0.0f);    // (a_f(k),  0)

                // h-broadcast: 16 pipelined shfl -> 8 (even,odd) pairs.
                ull hp[NH / 2];
                #pragma unroll
                for (int p = 0; p < NH / 2; ++p) {
                    const float h0 = __shfl_sync(FULLMASK, h, 2 * p);
                    const float h1 = __shfl_sync(FULLMASK, h, 2 * p + 1);
                    hp[p] = pack2(h0, h1);
                }

                // Matvec: 3 gate-sets x 8 fma2, 6 split chains (depth 4).
                ull accA1 = mul2(wA2[1], hp[1]);
                ull accB1 = mul2(wB2[1], hp[1]);
                ull accC1 = mul2(wC2[1], hp[1]);
                fma2(accA0, wA2[0], hp[0]);  fma2(accB0, wB2[0], hp[0]);
                fma2(accC0, wC2[0], hp[0]);
                fma2(accA0, wA2[2], hp[2]);  fma2(accB0, wB2[2], hp[2]);
                fma2(accC0, wC2[2], hp[2]);
                fma2(accA1, wA2[3], hp[3]);  fma2(accB1, wB2[3], hp[3]);
                fma2(accC1, wC2[3], hp[3]);
                fma2(accA0, wA2[4], hp[4]);  fma2(accB0, wB2[4], hp[4]);
                fma2(accC0, wC2[4], hp[4]);
                fma2(accA1, wA2[5], hp[5]);  fma2(accB1, wB2[5], hp[5]);
                fma2(accC1, wC2[5], hp[5]);
                fma2(accA0, wA2[6], hp[6]);  fma2(accB0, wB2[6], hp[6]);
                fma2(accC0, wC2[6], hp[6]);
                fma2(accA1, wA2[7], hp[7]);  fma2(accB1, wB2[7], hp[7]);
                fma2(accC1, wC2[7], hp[7]);

                const float SA = hsum2(add2(accA0, accA1)); // 0.5*(i|f)
                const float SB = hsum2(add2(accB0, accB1)); // g | 0.5*o
                const float SC = hsum2(add2(accC0, accC1)); // 0.5*f(k)

                const float thA = tanh_fast(SA);   // -> sigmoid(i) (lower)
                const float thB = tanh_fast(SB);   // tanh(g) | -> sigmoid(o)
                const float thC = tanh_fast(SC);   // -> sigmoid(f), LOCAL

                // Upper lanes finish so off-chain; shfl hides under c-path.
                const float soAll = fmaf(0.5f, thB, 0.5f);
                const float so = __shfl_down_sync(FULLMASK, soAll, 16);

                // Cell update (real state in lanes 0..15).
                const float si = fmaf(0.5f, thA, 0.5f);
                const float sf = fmaf(0.5f, thC, 0.5f);
                const float ig = si * thB;
                c = fmaf(sf, c, ig);
                const float tc = tanh_fast(c);
                h = so * tc;        // so arrived during tanh(c)
            }
        } else if (w + 1 < NWND) {
            fill_window(w + 1);
        }
        __syncthreads();
    }

    // Epilogue (off-chain, accurate math).
    if (warp == 0 && lane < NH) hfin[lane] = h;
    __syncthreads();
    if (tid < 5) {
        float acc = b_lin[tid];
        #pragma unroll
        for (int j = 0; j < NH; ++j)
            acc = fmaf(W_lin[tid * NH + j], hfin[j], acc);
        out[tid] = sig_acc(acc);
    }
}

extern "C" void kernel_launch(void* const* d_in, const int* in_sizes, int n_in,
                              void* d_out, int out_size) {
    (void)in_sizes; (void)n_in; (void)out_size;
    const float* x     = (const float*)d_in[0];
    const float* W_ih  = (const float*)d_in[1];
    const float* W_hh  = (const float*)d_in[2];
    const float* b_ih  = (const float*)d_in[3];
    const float* b_hh  = (const float*)d_in[4];
    const float* W_lin = (const float*)d_in[5];
    const float* b_lin = (const float*)d_in[6];
    float* out = (float*)d_out;

    lstm_last_row_kernel<<<1, 64>>>(x, W_ih, W_hh, b_ih, b_hh, W_lin, b_lin, out);
}

// round 10
// speedup vs baseline: 1.0311x; 1.0311x over previous
#include <cuda_runtime.h>

// Problem constants (fixed by the reference).
#define NB 4096
#define NT 512
#define NI 5
#define NH 16
#define FULLMASK 0xffffffffu

typedef unsigned long long ull;

// ---- fast activations ----
__device__ __forceinline__ float tanh_fast(float x) {
    float y;
    asm("tanh.approx.f32 %0, %1;" : "=f"(y) : "f"(x));
    return y;
}
__device__ __forceinline__ float sig_acc(float x) {   // epilogue only
    float e = __expf(-x);
    return __fdividef(1.0f, 1.0f + e);
}

// ---- packed f32x2 helpers (Blackwell FFMA2) ----
__device__ __forceinline__ ull pack2(float lo, float hi) {
    ull r;
    asm("mov.b64 %0, {%1, %2};" : "=l"(r) : "f"(lo), "f"(hi));
    return r;
}
__device__ __forceinline__ void unpack2(ull v, float& lo, float& hi) {
    asm("mov.b64 {%0, %1}, %2;" : "=f"(lo), "=f"(hi) : "l"(v));
}
__device__ __forceinline__ void fma2(ull& acc, ull a, ull b) {
    asm("fma.rn.f32x2 %0, %1, %2, %0;" : "+l"(acc) : "l"(a), "l"(b));
}
__device__ __forceinline__ ull add2(ull a, ull b) {
    ull r;
    asm("add.rn.f32x2 %0, %1, %2;" : "=l"(r) : "l"(a), "l"(b));
    return r;
}

// Single-warp LSTM over the ONLY batch row that matters (b = NB-1).
// EXACT R2 structure (proven fastest): lane L owns gate L (i|f) and L+32
// (g|o); 16-shfl h-broadcast; shfl_down ships f/o tanh-halves.
// New vs R2: (1) sigmoid-gate weights pre-scaled by 0.5 so tanh args need
// no multiply; (2) c-update re-associated so only ONE fma depends on the
// shfl-shipped thF.
__global__ void __launch_bounds__(32, 1) lstm_last_row_kernel(
    const float* __restrict__ x,      // (B, T, I)
    const float* __restrict__ W_ih,   // (64, 5)
    const float* __restrict__ W_hh,   // (64, 16)
    const float* __restrict__ b_ih,   // (64,)
    const float* __restrict__ b_hh,   // (64,)
    const float* __restrict__ W_lin,  // (5, 16)
    const float* __restrict__ b_lin,  // (5,)
    float* __restrict__ out)          // (5,)
{
    __shared__ float xs[NT * NI];     // 2560 floats = 10 KB
    const int lane = threadIdx.x;

    // Stage x[B-1, :, :] into smem.
    {
        const float4* src = reinterpret_cast<const float4*>(
            x + (size_t)(NB - 1) * NT * NI);
        float4* dst = reinterpret_cast<float4*>(xs);
        #pragma unroll
        for (int i = lane; i < (NT * NI) / 4; i += 32) dst[i] = src[i];
    }

    const int g0 = lane;        // i_k (lane<16) or f_k (lane>=16) -> 0.5-scaled
    const int g1 = lane + 32;   // g_k (lane<16, unscaled) or o_k (0.5-scaled)
    const float sB = (lane < 16) ? 1.0f : 0.5f;

    // Recurrent weights, (even,odd)-packed, PRE-SCALED.
    ull wA2[NH / 2], wB2[NH / 2];
    #pragma unroll
    for (int p = 0; p < NH / 2; ++p) {
        wA2[p] = pack2(0.5f * W_hh[g0 * NH + 2 * p],
                       0.5f * W_hh[g0 * NH + 2 * p + 1]);
        wB2[p] = pack2(sB * W_hh[g1 * NH + 2 * p],
                       sB * W_hh[g1 * NH + 2 * p + 1]);
    }
    float wiA[NI], wiB[NI];
    #pragma unroll
    for (int i = 0; i < NI; ++i) {
        wiA[i] = 0.5f * W_ih[g0 * NI + i];
        wiB[i] = sB   * W_ih[g1 * NI + i];
    }
    const float bbA = 0.5f * (b_ih[g0] + b_hh[g0]);
    const float bbB = sB   * (b_ih[g1] + b_hh[g1]);

    float h = 0.0f, c = 0.0f, ch = 0.0f;   // ch = 0.5f * c (kept in sync)

    __syncwarp();  // xs visible to all lanes

    #pragma unroll 2
    for (int t = 0; t < NT; ++t) {
        const float* xt = &xs[t * NI];

        // Input projection + biases (independent of h -> hides under chain).
        float a0 = bbA, a1 = bbB;
        #pragma unroll
        for (int i = 0; i < NI; ++i) {
            const float xv = xt[i];
            a0 = fmaf(wiA[i], xv, a0);
            a1 = fmaf(wiB[i], xv, a1);
        }

        // Recurrent matvec: 16 shfl broadcast, 16 packed FMAs, 4 chains.
        ull accA = pack2(a0, 0.0f);
        ull accB = pack2(a1, 0.0f);
        ull accA1 = pack2(0.0f, 0.0f);
        ull accB1 = pack2(0.0f, 0.0f);
        #pragma unroll
        for (int p = 0; p < NH / 2; p += 2) {
            const float hj0 = __shfl_sync(FULLMASK, h, 2 * p);
            const float hj1 = __shfl_sync(FULLMASK, h, 2 * p + 1);
            const float hj2 = __shfl_sync(FULLMASK, h, 2 * p + 2);
            const float hj3 = __shfl_sync(FULLMASK, h, 2 * p + 3);
            const ull hp0 = pack2(hj0, hj1);
            const ull hp1 = pack2(hj2, hj3);
            fma2(accA,  wA2[p],     hp0);
            fma2(accB,  wB2[p],     hp0);
            fma2(accA1, wA2[p + 1], hp1);
            fma2(accB1, wB2[p + 1], hp1);
        }
        float xA, yA, xB, yB;
        unpack2(add2(accA, accA1), xA, yA);
        unpack2(add2(accB, accB1), xB, yB);

        // Pre-scaled args: tanh takes the sum directly (no multiply).
        const float thA = tanh_fast(xA + yA);   // -> sigmoid(i) | sigmoid(f)
        const float thB = tanh_fast(xB + yB);   // tanh(g) | -> sigmoid(o)

        // Ship f/o tanh-halves down to the state lanes.
        const float thF = __shfl_down_sync(FULLMASK, thA, 16);
        const float thO = __shfl_down_sync(FULLMASK, thB, 16);

        // Cell update (state lanes 0..15; upper lanes compute junk).
        const float si = fmaf(0.5f, thA, 0.5f);       // sigmoid(i)
        const float ig = si * thB;                    // i * g
        // c' = sf*c + ig,  sf = 0.5*thF + 0.5
        //    = fma(0.5*c, thF, fma(0.5, c, ig))  -> depth after thF = 4.
        const float inner = fmaf(0.5f, c, ig);
        c  = fmaf(ch, thF, inner);
        ch = 0.5f * c;                                // off-chain for next step
        const float tc = tanh_fast(c);
        const float so = fmaf(0.5f, thO, 0.5f);       // ready during tanh(c)
        h = so * tc;
    }

    // Epilogue (off-chain, accurate math).
    float hv[NH];
    #pragma unroll
    for (int j = 0; j < NH; ++j) hv[j] = __shfl_sync(FULLMASK, h, j);

    if (lane < 5) {
        float acc = b_lin[lane];
        #pragma unroll
        for (int k = 0; k < NH; ++k)
            acc = fmaf(W_lin[lane * NH + k], hv[k], acc);
        out[lane] = sig_acc(acc);
    }
}

extern "C" void kernel_launch(void* const* d_in, const int* in_sizes, int n_in,
                              void* d_out, int out_size) {
    (void)in_sizes; (void)n_in; (void)out_size;
    const float* x     = (const float*)d_in[0];
    const float* W_ih  = (const float*)d_in[1];
    const float* W_hh  = (const float*)d_in[2];
    const float* b_ih  = (const float*)d_in[3];
    const float* b_hh  = (const float*)d_in[4];
    const float* W_lin = (const float*)d_in[5];
    const float* b_lin = (const float*)d_in[6];
    float* out = (float*)d_out;

    lstm_last_row_kernel<<<1, 32>>>(x, W_ih, W_hh, b_ih, b_hh, W_lin, b_lin, out);
}

// round 12
// speedup vs baseline: 1.0370x; 1.0058x over previous
#include <cuda_runtime.h>

// Problem constants (fixed by the reference).
#define NB 4096
#define NT 512
#define NI 5
#define XST 8                 // padded x-row stride -> LDS.128-aligned rows
#define NH 16
#define FULLMASK 0xffffffffu

typedef unsigned long long ull;

// ---- fast activations ----
__device__ __forceinline__ float tanh_fast(float x) {
    float y;
    asm("tanh.approx.f32 %0, %1;" : "=f"(y) : "f"(x));
    return y;
}
__device__ __forceinline__ float sig_acc(float x) {   // epilogue only
    float e = __expf(-x);
    return __fdividef(1.0f, 1.0f + e);
}

// ---- packed f32x2 helpers (Blackwell FFMA2) ----
__device__ __forceinline__ ull pack2(float lo, float hi) {
    ull r;
    asm("mov.b64 %0, {%1, %2};" : "=l"(r) : "f"(lo), "f"(hi));
    return r;
}
__device__ __forceinline__ void unpack2(ull v, float& lo, float& hi) {
    asm("mov.b64 {%0, %1}, %2;" : "=f"(lo), "=f"(hi) : "l"(v));
}
__device__ __forceinline__ void fma2(ull& acc, ull a, ull b) {
    asm("fma.rn.f32x2 %0, %1, %2, %0;" : "+l"(acc) : "l"(a), "l"(b));
}
__device__ __forceinline__ ull mul2(ull a, ull b) {
    ull r;
    asm("mul.rn.f32x2 %0, %1, %2;" : "=l"(r) : "l"(a), "l"(b));
    return r;
}
__device__ __forceinline__ ull add2(ull a, ull b) {
    ull r;
    asm("add.rn.f32x2 %0, %1, %2;" : "=l"(r) : "l"(a), "l"(b));
    return r;
}

// Single-warp LSTM over the ONLY batch row that matters (b = NB-1).
// Structure frozen at the R2 optimum: lane L owns gate L (i|f) and L+32
// (g|o); 16-shfl h-broadcast; shfl_down ships f/o tanh-halves.
// This round: ISSUE-ORDER surgery only — broadcast shfls open the loop
// body (issue right after h), xproj compressed to LDS.128+LDS.32 and moved
// into the shfl latency shadow, unroll 4 for cross-iteration overlap.
__global__ void __launch_bounds__(32, 1) lstm_last_row_kernel(
    const float* __restrict__ x,      // (B, T, I)
    const float* __restrict__ W_ih,   // (64, 5)
    const float* __restrict__ W_hh,   // (64, 16)
    const float* __restrict__ b_ih,   // (64,)
    const float* __restrict__ b_hh,   // (64,)
    const float* __restrict__ W_lin,  // (5, 16)
    const float* __restrict__ b_lin,  // (5,)
    float* __restrict__ out)          // (5,)
{
    __shared__ __align__(16) float xs[NT * XST];   // 16 KB padded x rows
    const int lane = threadIdx.x;

    // Stage x[B-1, :, :] into padded smem rows.
    {
        const float* src = x + (size_t)(NB - 1) * NT * NI;
        #pragma unroll 4
        for (int i = lane; i < NT * NI; i += 32) {
            const int t = i / NI, j = i - t * NI;
            xs[t * XST + j] = src[i];
        }
    }

    const int g0 = lane;        // i_k (lane<16) or f_k (lane>=16) -> 0.5-scaled
    const int g1 = lane + 32;   // g_k (lane<16, unscaled) or o_k (0.5-scaled)
    const float sB = (lane < 16) ? 1.0f : 0.5f;

    // Recurrent weights, (even,odd)-packed, PRE-SCALED.
    ull wA2[NH / 2], wB2[NH / 2];
    #pragma unroll
    for (int p = 0; p < NH / 2; ++p) {
        wA2[p] = pack2(0.5f * W_hh[g0 * NH + 2 * p],
                       0.5f * W_hh[g0 * NH + 2 * p + 1]);
        wB2[p] = pack2(sB * W_hh[g1 * NH + 2 * p],
                       sB * W_hh[g1 * NH + 2 * p + 1]);
    }
    float wiA[NI], wiB[NI];
    #pragma unroll
    for (int i = 0; i < NI; ++i) {
        wiA[i] = 0.5f * W_ih[g0 * NI + i];
        wiB[i] = sB   * W_ih[g1 * NI + i];
    }
    const float bbA = 0.5f * (b_ih[g0] + b_hh[g0]);
    const float bbB = sB   * (b_ih[g1] + b_hh[g1]);

    float h = 0.0f, c = 0.0f, ch = 0.0f;   // ch = 0.5f * c (kept in sync)

    __syncwarp();  // xs visible to all lanes

    #pragma unroll 4
    for (int t = 0; t < NT; ++t) {
        // ---- Broadcast FIRST: 16 shfls issue immediately after h. ----
        const float hj0  = __shfl_sync(FULLMASK, h, 0);
        const float hj1  = __shfl_sync(FULLMASK, h, 1);
        const float hj2  = __shfl_sync(FULLMASK, h, 2);
        const float hj3  = __shfl_sync(FULLMASK, h, 3);
        const float hj4  = __shfl_sync(FULLMASK, h, 4);
        const float hj5  = __shfl_sync(FULLMASK, h, 5);
        const float hj6  = __shfl_sync(FULLMASK, h, 6);
        const float hj7  = __shfl_sync(FULLMASK, h, 7);
        const float hj8  = __shfl_sync(FULLMASK, h, 8);
        const float hj9  = __shfl_sync(FULLMASK, h, 9);
        const float hj10 = __shfl_sync(FULLMASK, h, 10);
        const float hj11 = __shfl_sync(FULLMASK, h, 11);
        const float hj12 = __shfl_sync(FULLMASK, h, 12);
        const float hj13 = __shfl_sync(FULLMASK, h, 13);
        const float hj14 = __shfl_sync(FULLMASK, h, 14);
        const float hj15 = __shfl_sync(FULLMASK, h, 15);

        // ---- xproj in the shfl shadow: LDS.128 + LDS.32 + 10 FMA. ----
        const float4 xq = *reinterpret_cast<const float4*>(&xs[t * XST]);
        const float  x4 = xs[t * XST + 4];
        float a0 = bbA, a1 = bbB;
        a0 = fmaf(wiA[0], xq.x, a0);  a1 = fmaf(wiB[0], xq.x, a1);
        a0 = fmaf(wiA[1], xq.y, a0);  a1 = fmaf(wiB[1], xq.y, a1);
        a0 = fmaf(wiA[2], xq.z, a0);  a1 = fmaf(wiB[2], xq.z, a1);
        a0 = fmaf(wiA[3], xq.w, a0);  a1 = fmaf(wiB[3], xq.w, a1);
        a0 = fmaf(wiA[4], x4,   a0);  a1 = fmaf(wiB[4], x4,   a1);

        // ---- Pack pairs as shfl results land. ----
        const ull hp0 = pack2(hj0,  hj1);
        const ull hp1 = pack2(hj2,  hj3);
        const ull hp2 = pack2(hj4,  hj5);
        const ull hp3 = pack2(hj6,  hj7);
        const ull hp4 = pack2(hj8,  hj9);
        const ull hp5 = pack2(hj10, hj11);
        const ull hp6 = pack2(hj12, hj13);
        const ull hp7 = pack2(hj14, hj15);

        // ---- Matvec: 16 packed ops, 4 split chains (mul2-first). ----
        ull accA  = pack2(a0, 0.0f);
        ull accB  = pack2(a1, 0.0f);
        ull accA1 = mul2(wA2[1], hp1);
        ull accB1 = mul2(wB2[1], hp1);
        fma2(accA,  wA2[0], hp0);  fma2(accB,  wB2[0], hp0);
        fma2(accA,  wA2[2], hp2);  fma2(accB,  wB2[2], hp2);
        fma2(accA1, wA2[3], hp3);  fma2(accB1, wB2[3], hp3);
        fma2(accA,  wA2[4], hp4);  fma2(accB,  wB2[4], hp4);
        fma2(accA1, wA2[5], hp5);  fma2(accB1, wB2[5], hp5);
        fma2(accA,  wA2[6], hp6);  fma2(accB,  wB2[6], hp6);
        fma2(accA1, wA2[7], hp7);  fma2(accB1, wB2[7], hp7);

        float xA, yA, xB, yB;
        unpack2(add2(accA, accA1), xA, yA);
        unpack2(add2(accB, accB1), xB, yB);

        // Pre-scaled args: tanh takes the sum directly.
        const float thA = tanh_fast(xA + yA);   // -> sigmoid(i) | sigmoid(f)
        const float thB = tanh_fast(xB + yB);   // tanh(g) | -> sigmoid(o)

        // Ship f/o tanh-halves down to the state lanes.
        const float thF = __shfl_down_sync(FULLMASK, thA, 16);
        const float thO = __shfl_down_sync(FULLMASK, thB, 16);

        // Cell update (state lanes 0..15; upper lanes compute junk).
        const float si = fmaf(0.5f, thA, 0.5f);       // sigmoid(i)
        const float ig = si * thB;                    // i * g
        const float inner = fmaf(0.5f, c, ig);        // 0.5*c + ig
        c  = fmaf(ch, thF, inner);                    // depth-4 after thF
        ch = 0.5f * c;                                // off-chain for next step
        const float tc = tanh_fast(c);
        const float so = fmaf(0.5f, thO, 0.5f);       // ready during tanh(c)
        h = so * tc;
    }

    // Epilogue (off-chain, accurate math).
    float hv[NH];
    #pragma unroll
    for (int j = 0; j < NH; ++j) hv[j] = __shfl_sync(FULLMASK, h, j);

    if (lane < 5) {
        float acc = b_lin[lane];
        #pragma unroll
        for (int k = 0; k < NH; ++k)
            acc = fmaf(W_lin[lane * NH + k], hv[k], acc);
        out[lane] = sig_acc(acc);
    }
}

extern "C" void kernel_launch(void* const* d_in, const int* in_sizes, int n_in,
                              void* d_out, int out_size) {
    (void)in_sizes; (void)n_in; (void)out_size;
    const float* x     = (const float*)d_in[0];
    const float* W_ih  = (const float*)d_in[1];
    const float* W_hh  = (const float*)d_in[2];
    const float* b_ih  = (const float*)d_in[3];
    const float* b_hh  = (const float*)d_in[4];
    const float* W_lin = (const float*)d_in[5];
    const float* b_lin = (const float*)d_in[6];
    float* out = (float*)d_out;

    lstm_last_row_kernel<<<1, 32>>>(x, W_ih, W_hh, b_ih, b_hh, W_lin, b_lin, out);
}

// round 14
// speedup vs baseline: 1.0775x; 1.0391x over previous
#include <cuda_runtime.h>

// Problem constants (fixed by the reference).
#define NB 4096
#define NT 512
#define NI 5
#define NH 16
#define FULLMASK 0xffffffffu

// ---- fast activations ----
__device__ __forceinline__ float tanh_fast(float x) {
    float y;
    asm("tanh.approx.f32 %0, %1;" : "=f"(y) : "f"(x));
    return y;
}
__device__ __forceinline__ float sig_fast(float x) {
    // sigmoid(x) = 0.5*tanh(0.5*x) + 0.5
    return fmaf(0.5f, tanh_fast(0.5f * x), 0.5f);
}
// accurate sigmoid for the (off-chain) epilogue
__device__ __forceinline__ float sig_acc(float x) {
    float e = __expf(-x);
    return __fdividef(1.0f, 1.0f + e);
}

// ---- packed f32x2 helpers (Blackwell FFMA2; ptxas never auto-fuses) ----
__device__ __forceinline__ unsigned long long pack2(float lo, float hi) {
    unsigned long long r;
    asm("mov.b64 %0, {%1, %2};" : "=l"(r) : "f"(lo), "f"(hi));
    return r;
}
__device__ __forceinline__ void unpack2(unsigned long long v, float& lo, float& hi) {
    asm("mov.b64 {%0, %1}, %2;" : "=f"(lo), "=f"(hi) : "l"(v));
}
__device__ __forceinline__ void fma2(unsigned long long& acc,
                                     unsigned long long a,
                                     unsigned long long b) {
    asm("fma.rn.f32x2 %0, %1, %2, %0;" : "+l"(acc) : "l"(a), "l"(b));
}

// Single-warp LSTM over the ONLY batch row that matters (b = NB-1).
// Lane L owns gate L (i for L<16, f for L>=16) and gate L+32 (g / o).
// EXACT R2 kernel (measured best, 54.1us) with ONE delta: unroll 2 -> 8
// to amortize loop BRA/index overhead (body ~9KB, fits I$ L0+prefetch).
__global__ void __launch_bounds__(32, 1) lstm_last_row_kernel(
    const float* __restrict__ x,      // (B, T, I)
    const float* __restrict__ W_ih,   // (64, 5)
    const float* __restrict__ W_hh,   // (64, 16)
    const float* __restrict__ b_ih,   // (64,)
    const float* __restrict__ b_hh,   // (64,)
    const float* __restrict__ W_lin,  // (5, 16)
    const float* __restrict__ b_lin,  // (5,)
    float* __restrict__ out)          // (5,)
{
    __shared__ float xs[NT * NI];     // 2560 floats = 10 KB
    const int lane = threadIdx.x;

    // Stage x[B-1, :, :] into smem.
    {
        const float4* src = reinterpret_cast<const float4*>(
            x + (size_t)(NB - 1) * NT * NI);
        float4* dst = reinterpret_cast<float4*>(xs);
        #pragma unroll
        for (int i = lane; i < (NT * NI) / 4; i += 32) dst[i] = src[i];
    }

    const int g0 = lane;        // i_k (lane<16) or f_k (lane>=16)
    const int g1 = lane + 32;   // g_k (lane<16) or o_k (lane>=16)

    // Recurrent weights, packed in (even,odd) f32x2 pairs.
    unsigned long long wA2[NH / 2], wB2[NH / 2];
    #pragma unroll
    for (int p = 0; p < NH / 2; ++p) {
        wA2[p] = pack2(W_hh[g0 * NH + 2 * p], W_hh[g0 * NH + 2 * p + 1]);
        wB2[p] = pack2(W_hh[g1 * NH + 2 * p], W_hh[g1 * NH + 2 * p + 1]);
    }
    float wiA[NI], wiB[NI];
    #pragma unroll
    for (int i = 0; i < NI; ++i) {
        wiA[i] = W_ih[g0 * NI + i];
        wiB[i] = W_ih[g1 * NI + i];
    }
    const float bbA = b_ih[g0] + b_hh[g0];
    const float bbB = b_ih[g1] + b_hh[g1];

    // thB scale: g (lane<16) wants tanh(x) -> aB=1; o is sigmoid -> aB=0.5.
    const float aB = (lane < 16) ? 1.0f : 0.5f;

    float h = 0.0f, c = 0.0f;

    __syncwarp();  // xs visible to all lanes

    #pragma unroll 8
    for (int t = 0; t < NT; ++t) {
        const float* xt = &xs[t * NI];

        // Input projection + biases (independent of h -> hidden by chain).
        float a0 = bbA, a1 = bbB;
        #pragma unroll
        for (int i = 0; i < NI; ++i) {
            const float xv = xt[i];
            a0 = fmaf(wiA[i], xv, a0);
            a1 = fmaf(wiB[i], xv, a1);
        }

        // Recurrent matvec with packed FFMA2: 8+8 packed FMAs.
        unsigned long long accA = pack2(a0, 0.0f);
        unsigned long long accB = pack2(a1, 0.0f);
        #pragma unroll
        for (int p = 0; p < NH / 2; ++p) {
            const float hj0 = __shfl_sync(FULLMASK, h, 2 * p);
            const float hj1 = __shfl_sync(FULLMASK, h, 2 * p + 1);
            const unsigned long long hp = pack2(hj0, hj1);
            fma2(accA, wA2[p], hp);
            fma2(accB, wB2[p], hp);
        }
        float xA, yA, xB, yB;
        unpack2(accA, xA, yA);
        unpack2(accB, xB, yB);
        const float gA = xA + yA;   // i_k | f_k pre-activation
        const float gB = xB + yB;   // g_k | o_k pre-activation

        const float act0 = sig_fast(gA);                           // sig(i|f)
        const float act1 = fmaf(aB, tanh_fast(aB * gB), (lane < 16) ? 0.0f : 0.5f);
        // lanes<16: 1*tanh(gB)+0 = tanh(g);  lanes>=16: 0.5*tanh(gB/2)+0.5 = sig(o)

        // Fetch f_k / o_k from lane k+16 (upper lanes compute dead values).
        const float fg = __shfl_down_sync(FULLMASK, act0, 16);
        const float og = __shfl_down_sync(FULLMASK, act1, 16);

        // Cell update (real state lives in lanes 0..15).
        c = fmaf(fg, c, act0 * act1);
        const float tc = tanh_fast(c);
        h = og * tc;
    }

    // Epilogue (off-chain, accurate math).
    float hv[NH];
    #pragma unroll
    for (int j = 0; j < NH; ++j) hv[j] = __shfl_sync(FULLMASK, h, j);

    if (lane < 5) {
        float acc = b_lin[lane];
        #pragma unroll
        for (int k = 0; k < NH; ++k)
            acc = fmaf(W_lin[lane * NH + k], hv[k], acc);
        out[lane] = sig_acc(acc);
    }
}

extern "C" void kernel_launch(void* const* d_in, const int* in_sizes, int n_in,
                              void* d_out, int out_size) {
    (void)in_sizes; (void)n_in; (void)out_size;
    const float* x     = (const float*)d_in[0];
    const float* W_ih  = (const float*)d_in[1];
    const float* W_hh  = (const float*)d_in[2];
    const float* b_ih  = (const float*)d_in[3];
    const float* b_hh  = (const float*)d_in[4];
    const float* W_lin = (const float*)d_in[5];
    const float* b_lin = (const float*)d_in[6];
    float* out = (float*)d_out;

    lstm_last_row_kernel<<<1, 32>>>(x, W_ih, W_hh, b_ih, b_hh, W_lin, b_lin, out);
}

// round 15
// speedup vs baseline: 1.1075x; 1.0278x over previous
#include <cuda_runtime.h>

// Problem constants (fixed by the reference).
#define NB 4096
#define NT 512
#define NI 5
#define NH 16
#define FULLMASK 0xffffffffu

// ---- fast activations ----
__device__ __forceinline__ float tanh_fast(float x) {
    float y;
    asm("tanh.approx.f32 %0, %1;" : "=f"(y) : "f"(x));
    return y;
}
__device__ __forceinline__ float sig_fast(float x) {
    // sigmoid(x) = 0.5*tanh(0.5*x) + 0.5
    return fmaf(0.5f, tanh_fast(0.5f * x), 0.5f);
}
// accurate sigmoid for the (off-chain) epilogue
__device__ __forceinline__ float sig_acc(float x) {
    float e = __expf(-x);
    return __fdividef(1.0f, 1.0f + e);
}

// ---- packed f32x2 helpers (Blackwell FFMA2; ptxas never auto-fuses) ----
__device__ __forceinline__ unsigned long long pack2(float lo, float hi) {
    unsigned long long r;
    asm("mov.b64 %0, {%1, %2};" : "=l"(r) : "f"(lo), "f"(hi));
    return r;
}
__device__ __forceinline__ void unpack2(unsigned long long v, float& lo, float& hi) {
    asm("mov.b64 {%0, %1}, %2;" : "=f"(lo), "=f"(hi) : "l"(v));
}
__device__ __forceinline__ void fma2(unsigned long long& acc,
                                     unsigned long long a,
                                     unsigned long long b) {
    asm("fma.rn.f32x2 %0, %1, %2, %0;" : "+l"(acc) : "l"(a), "l"(b));
}

// Single-warp LSTM over the ONLY batch row that matters (b = NB-1).
// Lane L owns gate L (i for L<16, f for L>=16) and gate L+32 (g / o).
// EXACT R14 kernel (measured best, 53.2us) with ONE delta: unroll 8 -> 16
// (branch amortization; ~18KB body fits L1.5 I$ with prefetch overlap).
__global__ void __launch_bounds__(32, 1) lstm_last_row_kernel(
    const float* __restrict__ x,      // (B, T, I)
    const float* __restrict__ W_ih,   // (64, 5)
    const float* __restrict__ W_hh,   // (64, 16)
    const float* __restrict__ b_ih,   // (64,)
    const float* __restrict__ b_hh,   // (64,)
    const float* __restrict__ W_lin,  // (5, 16)
    const float* __restrict__ b_lin,  // (5,)
    float* __restrict__ out)          // (5,)
{
    __shared__ float xs[NT * NI];     // 2560 floats = 10 KB
    const int lane = threadIdx.x;

    // Stage x[B-1, :, :] into smem.
    {
        const float4* src = reinterpret_cast<const float4*>(
            x + (size_t)(NB - 1) * NT * NI);
        float4* dst = reinterpret_cast<float4*>(xs);
        #pragma unroll
        for (int i = lane; i < (NT * NI) / 4; i += 32) dst[i] = src[i];
    }

    const int g0 = lane;        // i_k (lane<16) or f_k (lane>=16)
    const int g1 = lane + 32;   // g_k (lane<16) or o_k (lane>=16)

    // Recurrent weights, packed in (even,odd) f32x2 pairs.
    unsigned long long wA2[NH / 2], wB2[NH / 2];
    #pragma unroll
    for (int p = 0; p < NH / 2; ++p) {
        wA2[p] = pack2(W_hh[g0 * NH + 2 * p], W_hh[g0 * NH + 2 * p + 1]);
        wB2[p] = pack2(W_hh[g1 * NH + 2 * p], W_hh[g1 * NH + 2 * p + 1]);
    }
    float wiA[NI], wiB[NI];
    #pragma unroll
    for (int i = 0; i < NI; ++i) {
        wiA[i] = W_ih[g0 * NI + i];
        wiB[i] = W_ih[g1 * NI + i];
    }
    const float bbA = b_ih[g0] + b_hh[g0];
    const float bbB = b_ih[g1] + b_hh[g1];

    // thB scale: g (lane<16) wants tanh(x) -> aB=1; o is sigmoid -> aB=0.5.
    const float aB = (lane < 16) ? 1.0f : 0.5f;

    float h = 0.0f, c = 0.0f;

    __syncwarp();  // xs visible to all lanes

    #pragma unroll 16
    for (int t = 0; t < NT; ++t) {
        const float* xt = &xs[t * NI];

        // Input projection + biases (independent of h -> hidden by chain).
        float a0 = bbA, a1 = bbB;
        #pragma unroll
        for (int i = 0; i < NI; ++i) {
            const float xv = xt[i];
            a0 = fmaf(wiA[i], xv, a0);
            a1 = fmaf(wiB[i], xv, a1);
        }

        // Recurrent matvec with packed FFMA2: 8+8 packed FMAs.
        unsigned long long accA = pack2(a0, 0.0f);
        unsigned long long accB = pack2(a1, 0.0f);
        #pragma unroll
        for (int p = 0; p < NH / 2; ++p) {
            const float hj0 = __shfl_sync(FULLMASK, h, 2 * p);
            const float hj1 = __shfl_sync(FULLMASK, h, 2 * p + 1);
            const unsigned long long hp = pack2(hj0, hj1);
            fma2(accA, wA2[p], hp);
            fma2(accB, wB2[p], hp);
        }
        float xA, yA, xB, yB;
        unpack2(accA, xA, yA);
        unpack2(accB, xB, yB);
        const float gA = xA + yA;   // i_k | f_k pre-activation
        const float gB = xB + yB;   // g_k | o_k pre-activation

        const float act0 = sig_fast(gA);                           // sig(i|f)
        const float act1 = fmaf(aB, tanh_fast(aB * gB), (lane < 16) ? 0.0f : 0.5f);
        // lanes<16: 1*tanh(gB)+0 = tanh(g);  lanes>=16: 0.5*tanh(gB/2)+0.5 = sig(o)

        // Fetch f_k / o_k from lane k+16 (upper lanes compute dead values).
        const float fg = __shfl_down_sync(FULLMASK, act0, 16);
        const float og = __shfl_down_sync(FULLMASK, act1, 16);

        // Cell update (real state lives in lanes 0..15).
        c = fmaf(fg, c, act0 * act1);
        const float tc = tanh_fast(c);
        h = og * tc;
    }

    // Epilogue (off-chain, accurate math).
    float hv[NH];
    #pragma unroll
    for (int j = 0; j < NH; ++j) hv[j] = __shfl_sync(FULLMASK, h, j);

    if (lane < 5) {
        float acc = b_lin[lane];
        #pragma unroll
        for (int k = 0; k < NH; ++k)
            acc = fmaf(W_lin[lane * NH + k], hv[k], acc);
        out[lane] = sig_acc(acc);
    }
}

extern "C" void kernel_launch(void* const* d_in, const int* in_sizes, int n_in,
                              void* d_out, int out_size) {
    (void)in_sizes; (void)n_in; (void)out_size;
    const float* x     = (const float*)d_in[0];
    const float* W_ih  = (const float*)d_in[1];
    const float* W_hh  = (const float*)d_in[2];
    const float* b_ih  = (const float*)d_in[3];
    const float* b_hh  = (const float*)d_in[4];
    const float* W_lin = (const float*)d_in[5];
    const float* b_lin = (const float*)d_in[6];
    float* out = (float*)d_out;

    lstm_last_row_kernel<<<1, 32>>>(x, W_ih, W_hh, b_ih, b_hh, W_lin, b_lin, out);
}

// round 16
// speedup vs baseline: 1.1144x; 1.0062x over previous
#include <cuda_runtime.h>

// Problem constants (fixed by the reference).
#define NB 4096
#define NT 512
#define NI 5
#define NH 16
#define FULLMASK 0xffffffffu

// ---- fast activations ----
__device__ __forceinline__ float tanh_fast(float x) {
    float y;
    asm("tanh.approx.f32 %0, %1;" : "=f"(y) : "f"(x));
    return y;
}
__device__ __forceinline__ float sig_fast(float x) {
    // sigmoid(x) = 0.5*tanh(0.5*x) + 0.5
    return fmaf(0.5f, tanh_fast(0.5f * x), 0.5f);
}
// accurate sigmoid for the (off-chain) epilogue
__device__ __forceinline__ float sig_acc(float x) {
    float e = __expf(-x);
    return __fdividef(1.0f, 1.0f + e);
}

// ---- packed f32x2 helpers (Blackwell FFMA2; ptxas never auto-fuses) ----
__device__ __forceinline__ unsigned long long pack2(float lo, float hi) {
    unsigned long long r;
    asm("mov.b64 %0, {%1, %2};" : "=l"(r) : "f"(lo), "f"(hi));
    return r;
}
__device__ __forceinline__ void unpack2(unsigned long long v, float& lo, float& hi) {
    asm("mov.b64 {%0, %1}, %2;" : "=f"(lo), "=f"(hi) : "l"(v));
}
__device__ __forceinline__ void fma2(unsigned long long& acc,
                                     unsigned long long a,
                                     unsigned long long b) {
    asm("fma.rn.f32x2 %0, %1, %2, %0;" : "+l"(acc) : "l"(a), "l"(b));
}

// Single-warp LSTM over the ONLY batch row that matters (b = NB-1).
// Lane L owns gate L (i for L<16, f for L>=16) and gate L+32 (g / o).
// EXACT R15 kernel (measured best, 51.8us) with ONE delta: unroll 16 -> 32
// (branch amortization + deeper cross-iteration hoisting; ~36KB body sits
// in the L2-I$ transition — prefetch-overlapped on a steady loop).
__global__ void __launch_bounds__(32, 1) lstm_last_row_kernel(
    const float* __restrict__ x,      // (B, T, I)
    const float* __restrict__ W_ih,   // (64, 5)
    const float* __restrict__ W_hh,   // (64, 16)
    const float* __restrict__ b_ih,   // (64,)
    const float* __restrict__ b_hh,   // (64,)
    const float* __restrict__ W_lin,  // (5, 16)
    const float* __restrict__ b_lin,  // (5,)
    float* __restrict__ out)          // (5,)
{
    __shared__ float xs[NT * NI];     // 2560 floats = 10 KB
    const int lane = threadIdx.x;

    // Stage x[B-1, :, :] into smem.
    {
        const float4* src = reinterpret_cast<const float4*>(
            x + (size_t)(NB - 1) * NT * NI);
        float4* dst = reinterpret_cast<float4*>(xs);
        #pragma unroll
        for (int i = lane; i < (NT * NI) / 4; i += 32) dst[i] = src[i];
    }

    const int g0 = lane;        // i_k (lane<16) or f_k (lane>=16)
    const int g1 = lane + 32;   // g_k (lane<16) or o_k (lane>=16)

    // Recurrent weights, packed in (even,odd) f32x2 pairs.
    unsigned long long wA2[NH / 2], wB2[NH / 2];
    #pragma unroll
    for (int p = 0; p < NH / 2; ++p) {
        wA2[p] = pack2(W_hh[g0 * NH + 2 * p], W_hh[g0 * NH + 2 * p + 1]);
        wB2[p] = pack2(W_hh[g1 * NH + 2 * p], W_hh[g1 * NH + 2 * p + 1]);
    }
    float wiA[NI], wiB[NI];
    #pragma unroll
    for (int i = 0; i < NI; ++i) {
        wiA[i] = W_ih[g0 * NI + i];
        wiB[i] = W_ih[g1 * NI + i];
    }
    const float bbA = b_ih[g0] + b_hh[g0];
    const float bbB = b_ih[g1] + b_hh[g1];

    // thB scale: g (lane<16) wants tanh(x) -> aB=1; o is sigmoid -> aB=0.5.
    const float aB = (lane < 16) ? 1.0f : 0.5f;

    float h = 0.0f, c = 0.0f;

    __syncwarp();  // xs visible to all lanes

    #pragma unroll 32
    for (int t = 0; t < NT; ++t) {
        const float* xt = &xs[t * NI];

        // Input projection + biases (independent of h -> hidden by chain).
        float a0 = bbA, a1 = bbB;
        #pragma unroll
        for (int i = 0; i < NI; ++i) {
            const float xv = xt[i];
            a0 = fmaf(wiA[i], xv, a0);
            a1 = fmaf(wiB[i], xv, a1);
        }

        // Recurrent matvec with packed FFMA2: 8+8 packed FMAs.
        unsigned long long accA = pack2(a0, 0.0f);
        unsigned long long accB = pack2(a1, 0.0f);
        #pragma unroll
        for (int p = 0; p < NH / 2; ++p) {
            const float hj0 = __shfl_sync(FULLMASK, h, 2 * p);
            const float hj1 = __shfl_sync(FULLMASK, h, 2 * p + 1);
            const unsigned long long hp = pack2(hj0, hj1);
            fma2(accA, wA2[p], hp);
            fma2(accB, wB2[p], hp);
        }
        float xA, yA, xB, yB;
        unpack2(accA, xA, yA);
        unpack2(accB, xB, yB);
        const float gA = xA + yA;   // i_k | f_k pre-activation
        const float gB = xB + yB;   // g_k | o_k pre-activation

        const float act0 = sig_fast(gA);                           // sig(i|f)
        const float act1 = fmaf(aB, tanh_fast(aB * gB), (lane < 16) ? 0.0f : 0.5f);
        // lanes<16: 1*tanh(gB)+0 = tanh(g);  lanes>=16: 0.5*tanh(gB/2)+0.5 = sig(o)

        // Fetch f_k / o_k from lane k+16 (upper lanes compute dead values).
        const float fg = __shfl_down_sync(FULLMASK, act0, 16);
        const float og = __shfl_down_sync(FULLMASK, act1, 16);

        // Cell update (real state lives in lanes 0..15).
        c = fmaf(fg, c, act0 * act1);
        const float tc = tanh_fast(c);
        h = og * tc;
    }

    // Epilogue (off-chain, accurate math).
    float hv[NH];
    #pragma unroll
    for (int j = 0; j < NH; ++j) hv[j] = __shfl_sync(FULLMASK, h, j);

    if (lane < 5) {
        float acc = b_lin[lane];
        #pragma unroll
        for (int k = 0; k < NH; ++k)
            acc = fmaf(W_lin[lane * NH + k], hv[k], acc);
        out[lane] = sig_acc(acc);
    }
}

extern "C" void kernel_launch(void* const* d_in, const int* in_sizes, int n_in,
                              void* d_out, int out_size) {
    (void)in_sizes; (void)n_in; (void)out_size;
    const float* x     = (const float*)d_in[0];
    const float* W_ih  = (const float*)d_in[1];
    const float* W_hh  = (const float*)d_in[2];
    const float* b_ih  = (const float*)d_in[3];
    const float* b_hh  = (const float*)d_in[4];
    const float* W_lin = (const float*)d_in[5];
    const float* b_lin = (const float*)d_in[6];
    float* out = (float*)d_out;

    lstm_last_row_kernel<<<1, 32>>>(x, W_ih, W_hh, b_ih, b_hh, W_lin, b_lin, out);
}